// round 15
// baseline (speedup 1.0000x reference)
#include <cuda_runtime.h>
#include <cuda_fp16.h>
#include <mma.h>
#include <stdint.h>

using namespace nvcuda;

// GCN_57501022159512: 2-layer GCN, N=100000 nodes, E=1600000 edges, 64 -> 128 -> 128.
// h1 = relu(gcnconv(x, W1, b1)); t = batchnorm(h1); out = relu(gcnconv(t, W2, b2))
//
// R15: gather edge loop unrolled 8-wide (8 independent uint4 row loads in
// flight per lane = 128B, 2x R14). R14 showed gathers are bytes-in-flight
// limited, not traffic limited. 2-edge mid-tier + scalar tail.

#define NNODES 100000
#define NEDGES 1600000
#define FIN    64
#define FHID   128
#define BN_EPS 1e-5f

#define MPAD   100032          // NNODES rounded up to 64 (MMA M-tiles)

#define NB_SCAN 100
#define NODES_PER_BLK 1000     // NNODES / NB_SCAN, exact

#define GEMM1_BLOCKS (MPAD / 64)   // 1563 wmma tiles
#define DEG_BLOCKS   2048
#define FILL_BLOCKS  2048

// ---------------- scratch (device globals; no allocs allowed) ----------------
__device__ __half2 g_h1[MPAD * (FHID / 2)];    // x @ W1 (fp16, padded)
__device__ float   g_t [MPAD * FHID];          // gather1 output (fp32, padded)
__device__ __half2 g_h2[MPAD * (FHID / 2)];    // bn(t) @ W2 (fp16, padded)
__device__ __half  g_W1h[FIN * FHID];          // W1 in fp16 (row-major K x N)
__device__ __half  g_W2h[FHID * FHID];         // W2 in fp16 (row-major K x N)
__device__ float   g_dinv[NNODES];
__device__ int     g_deg [NNODES];
__device__ float   g_stats[2 * FHID];          // sum,sumsq
__device__ int     g_off [NNODES + 1];         // CSR offsets (by destination col)
__device__ int     g_cursor[NNODES];           // placement cursors
__device__ int2    g_csr[NEDGES];              // (src row, norm bits) sorted by dest
__device__ int     g_bsum[NB_SCAN];            // per-block degree sums
__device__ int     g_is64;

// ---------------- helpers ----------------

__device__ __forceinline__ void h16_to_f8(uint4 u, float4& a, float4& b) {
    const float2 f0 = __half22float2(*reinterpret_cast<__half2*>(&u.x));
    const float2 f1 = __half22float2(*reinterpret_cast<__half2*>(&u.y));
    const float2 f2 = __half22float2(*reinterpret_cast<__half2*>(&u.z));
    const float2 f3 = __half22float2(*reinterpret_cast<__half2*>(&u.w));
    a = make_float4(f0.x, f0.y, f1.x, f1.y);
    b = make_float4(f2.x, f2.y, f3.x, f3.y);
}

__device__ __forceinline__ void fma8(float4& a0, float4& a1, uint4 u, float nm) {
    float4 v0, v1;
    h16_to_f8(u, v0, v1);
    a0.x = fmaf(v0.x, nm, a0.x); a0.y = fmaf(v0.y, nm, a0.y);
    a0.z = fmaf(v0.z, nm, a0.z); a0.w = fmaf(v0.w, nm, a0.w);
    a1.x = fmaf(v1.x, nm, a1.x); a1.y = fmaf(v1.y, nm, a1.y);
    a1.z = fmaf(v1.z, nm, a1.z); a1.w = fmaf(v1.w, nm, a1.w);
}

__device__ __forceinline__ int load_idx(const void* ei, int pos, bool is64) {
    int v = is64 ? (int)((const long long*)ei)[pos] : ((const int*)ei)[pos];
    return min(max(v, 0), NNODES - 1);
}

// ---------------- setup ----------------

// zero deg/stats; convert W1, W2 -> fp16; block 0 detects edge dtype.
__global__ void k_zero_detect(const int* __restrict__ w,
                              const float* __restrict__ W1,
                              const float* __restrict__ W2) {
    const int idx = blockIdx.x * blockDim.x + threadIdx.x;
    const int stride = gridDim.x * blockDim.x;
    for (int j = idx; j < NNODES; j += stride) g_deg[j] = 0;
    for (int j = idx; j < FIN * FHID; j += stride) g_W1h[j] = __float2half_rn(W1[j]);
    for (int j = idx; j < FHID * FHID; j += stride) g_W2h[j] = __float2half_rn(W2[j]);
    if (idx < 2 * FHID) g_stats[idx] = 0.f;

    if (blockIdx.x == 0) {
        __shared__ int bad;
        if (threadIdx.x == 0) bad = 0;
        __syncthreads();
        for (int j = threadIdx.x; j < 1024; j += blockDim.x) {
            const int lo = w[2 * j], hi = w[2 * j + 1];
            if (hi != 0 || lo < 0 || lo >= NNODES) bad = 1;
        }
        __syncthreads();
        if (threadIdx.x == 0) g_is64 = (bad == 0) ? 1 : 0;
    }
}

// ---------------- fused gemm1 (wmma) + degree count ----------------
__global__ void __launch_bounds__(256) k_deg_gemm1(const float* __restrict__ x,
                                                   const void* __restrict__ ei) {
    if (blockIdx.x < GEMM1_BLOCKS) {
        __shared__ __half sA[64 * FIN];       // 8 KB
        const int t = threadIdx.x;
        const int warp = t >> 5;
        const int base = blockIdx.x * 64;

        for (int i = t; i < 64 * FIN; i += 256) {
            const int row = base + (i >> 6);
            sA[i] = (row < NNODES) ? __float2half_rn(x[(size_t)row * FIN + (i & 63)])
                                   : __float2half_rn(0.f);
        }
        __syncthreads();

        wmma::fragment<wmma::matrix_b, 16, 16, 16, __half, wmma::row_major> bf[4];
#pragma unroll
        for (int k = 0; k < 4; k++)
            wmma::load_matrix_sync(bf[k], g_W1h + (k * 16) * FHID + warp * 16, FHID);

        __half* h1 = reinterpret_cast<__half*>(g_h1);
#pragma unroll
        for (int m = 0; m < 4; m++) {
            wmma::fragment<wmma::accumulator, 16, 16, 16, float> acc;
            wmma::fill_fragment(acc, 0.0f);
#pragma unroll
            for (int k = 0; k < 4; k++) {
                wmma::fragment<wmma::matrix_a, 16, 16, 16, __half, wmma::row_major> af;
                wmma::load_matrix_sync(af, sA + (m * 16) * FIN + k * 16, FIN);
                wmma::mma_sync(acc, af, bf[k], acc);
            }
            wmma::fragment<wmma::accumulator, 16, 16, 16, __half> hacc;
#pragma unroll
            for (int i = 0; i < acc.num_elements; i++)
                hacc.x[i] = __float2half_rn(acc.x[i]);
            wmma::store_matrix_sync(h1 + (size_t)(base + m * 16) * FHID + warp * 16,
                                    hacc, FHID, wmma::mem_row_major);
        }
    } else {
        const int vb = blockIdx.x - GEMM1_BLOCKS;
        const int idx = vb * 256 + threadIdx.x;
        const int stride = DEG_BLOCKS * 256;
        const bool is64 = (g_is64 != 0);
        for (int e = idx; e < NEDGES; e += stride)
            atomicAdd(&g_deg[load_idx(ei, NEDGES + e, is64)], 1);
    }
}

// Stage A: per-block degree sums.
__global__ void k_scanA() {
    __shared__ int red[256];
    const int b = blockIdx.x;
    const int t = threadIdx.x;
    const int beg = b * NODES_PER_BLK;
    int s = 0;
    for (int i = t; i < NODES_PER_BLK; i += 256) s += g_deg[beg + i];
    red[t] = s;
    __syncthreads();
    for (int d = 128; d > 0; d >>= 1) {
        if (t < d) red[t] += red[t + d];
        __syncthreads();
    }
    if (t == 0) g_bsum[b] = red[0];
}

// Stage C: offsets + cursors + dinv (fused).
__global__ void k_scanC() {
    __shared__ int red[256];
    __shared__ int partial[256];
    __shared__ int s_base;
    const int b = blockIdx.x;
    const int t = threadIdx.x;
    const int beg = b * NODES_PER_BLK;

    int s = (t < b) ? g_bsum[t] : 0;
    red[t] = s;
    __syncthreads();
    for (int d = 128; d > 0; d >>= 1) {
        if (t < d) red[t] += red[t + d];
        __syncthreads();
    }
    if (t == 0) s_base = red[0];
    __syncthreads();

    const int cbeg = t * 4;
    int csum = 0;
    int dloc[4];
#pragma unroll
    for (int j = 0; j < 4; j++) {
        const int i = cbeg + j;
        dloc[j] = (i < NODES_PER_BLK) ? g_deg[beg + i] : 0;
        csum += dloc[j];
    }
    partial[t] = csum;
    __syncthreads();
    for (int d = 1; d < 256; d <<= 1) {
        int v = (t >= d) ? partial[t - d] : 0;
        __syncthreads();
        partial[t] += v;
        __syncthreads();
    }
    int run = s_base + ((t == 0) ? 0 : partial[t - 1]);
#pragma unroll
    for (int j = 0; j < 4; j++) {
        const int i = cbeg + j;
        if (i < NODES_PER_BLK) {
            g_off[beg + i] = run;
            g_cursor[beg + i] = run;
            g_dinv[beg + i] = rsqrtf((float)(dloc[j] + 1));
            run += dloc[j];
        }
    }
    if (b == NB_SCAN - 1 && t == 255) g_off[NNODES] = run;
}

// Counting sort directly from edge buffer.
__global__ void k_fillcsr(const void* __restrict__ ei) {
    const int idx = blockIdx.x * blockDim.x + threadIdx.x;
    const int stride = gridDim.x * blockDim.x;
    const bool is64 = (g_is64 != 0);
    for (int e = idx; e < NEDGES; e += stride) {
        const int r = load_idx(ei, e, is64);
        const int c = load_idx(ei, NEDGES + e, is64);
        const int pos = atomicAdd(&g_cursor[c], 1);
        const float nm = g_dinv[r] * g_dinv[c];
        g_csr[pos] = make_int2(r, __float_as_int(nm));
    }
}

// ---------------- GEMM2 on tensor cores (wmma fp16 / fp32 acc) ----------------
__global__ void __launch_bounds__(256) k_gemm2_mma(const float* __restrict__ gamma,
                                                   const float* __restrict__ beta) {
    __shared__ __half  sA[64 * FHID];       // 16 KB
    __shared__ float   sScale[FHID], sShift[FHID];
    const int t = threadIdx.x;
    const int warp = t >> 5;
    const int base = blockIdx.x * 64;

    if (t < FHID) {
        const float inv_n = 1.0f / (float)NNODES;
        const float mean = g_stats[t] * inv_n;
        const float var  = g_stats[FHID + t] * inv_n - mean * mean;
        const float rstd = rsqrtf(var + BN_EPS);
        const float sc = gamma[t] * rstd;
        sScale[t] = sc;
        sShift[t] = beta[t] - mean * sc;
    }
    __syncthreads();

    for (int i = t; i < 64 * FHID; i += 256) {
        const int c = i & 127;
        const float v = g_t[(size_t)(base + (i >> 7)) * FHID + c];
        sA[i] = __float2half_rn(fmaf(v, sScale[c], sShift[c]));
    }
    __syncthreads();

    wmma::fragment<wmma::matrix_b, 16, 16, 16, __half, wmma::row_major> bf[8];
#pragma unroll
    for (int k = 0; k < 8; k++)
        wmma::load_matrix_sync(bf[k], g_W2h + (k * 16) * FHID + warp * 16, FHID);

    __half* h2 = reinterpret_cast<__half*>(g_h2);
#pragma unroll
    for (int m = 0; m < 4; m++) {
        wmma::fragment<wmma::accumulator, 16, 16, 16, float> acc;
        wmma::fill_fragment(acc, 0.0f);
#pragma unroll
        for (int k = 0; k < 8; k++) {
            wmma::fragment<wmma::matrix_a, 16, 16, 16, __half, wmma::row_major> af;
            wmma::load_matrix_sync(af, sA + (m * 16) * FHID + k * 16, FHID);
            wmma::mma_sync(acc, af, bf[k], acc);
        }
        wmma::fragment<wmma::accumulator, 16, 16, 16, __half> hacc;
#pragma unroll
        for (int i = 0; i < acc.num_elements; i++)
            hacc.x[i] = __float2half_rn(acc.x[i]);
        wmma::store_matrix_sync(h2 + (size_t)(base + m * 16) * FHID + warp * 16,
                                hacc, FHID, wmma::mem_row_major);
    }
}

// ---------------- gathers: 16-lane virtual warps, uint4 rows, unroll x8 ------

__device__ __forceinline__ void gather_node16(const uint4* __restrict__ hp,
                                              int c, int lane,
                                              float4& acc0, float4& acc1) {
    const int beg = g_off[c], end = g_off[c + 1];
    const float dc = g_dinv[c];
    const float d2 = dc * dc;
    float4 h0, h1;
    h16_to_f8(hp[(size_t)c * 16 + lane], h0, h1);
    acc0 = make_float4(h0.x * d2, h0.y * d2, h0.z * d2, h0.w * d2);
    acc1 = make_float4(h1.x * d2, h1.y * d2, h1.z * d2, h1.w * d2);
    int i = beg;
    // 8-edge unroll: 8 independent row loads in flight per lane (128B).
    for (; i + 8 <= end; i += 8) {
        int2 e[8];
        uint4 u[8];
#pragma unroll
        for (int j = 0; j < 8; j++) e[j] = g_csr[i + j];
#pragma unroll
        for (int j = 0; j < 8; j++) u[j] = hp[(size_t)e[j].x * 16 + lane];
#pragma unroll
        for (int j = 0; j < 8; j++) fma8(acc0, acc1, u[j], __int_as_float(e[j].y));
    }
    // 2-edge mid-tier.
    for (; i + 2 <= end; i += 2) {
        const int2 e0 = g_csr[i];
        const int2 e1 = g_csr[i + 1];
        const uint4 u0 = hp[(size_t)e0.x * 16 + lane];
        const uint4 u1 = hp[(size_t)e1.x * 16 + lane];
        fma8(acc0, acc1, u0, __int_as_float(e0.y));
        fma8(acc0, acc1, u1, __int_as_float(e1.y));
    }
    for (; i < end; i++) {
        const int2 en = g_csr[i];
        fma8(acc0, acc1, hp[(size_t)en.x * 16 + lane], __int_as_float(en.y));
    }
}

// t[c] = relu(gather(h1) + b1); BN partial sums (block-level smem reduction).
__global__ void __launch_bounds__(256) k_gather1(const float* __restrict__ b1) {
    __shared__ float ssum[2 * FHID];
    const int lane = threadIdx.x & 15;
    const int vw   = (blockIdx.x * blockDim.x + threadIdx.x) >> 4;
    const int nvw  = (gridDim.x * blockDim.x) >> 4;
    const float4 bf0 = reinterpret_cast<const float4*>(b1)[2 * lane];
    const float4 bf1 = reinterpret_cast<const float4*>(b1)[2 * lane + 1];
    const uint4* hp = reinterpret_cast<const uint4*>(g_h1);
    float4* t4 = reinterpret_cast<float4*>(g_t);

    for (int i = threadIdx.x; i < 2 * FHID; i += 256) ssum[i] = 0.f;
    __syncthreads();

    float4 s0  = make_float4(0.f, 0.f, 0.f, 0.f), s1  = s0;
    float4 ss0 = s0, ss1 = s0;

    for (int c = vw; c < NNODES; c += nvw) {
        float4 a0, a1;
        gather_node16(hp, c, lane, a0, a1);
        a0.x = fmaxf(a0.x + bf0.x, 0.f); a0.y = fmaxf(a0.y + bf0.y, 0.f);
        a0.z = fmaxf(a0.z + bf0.z, 0.f); a0.w = fmaxf(a0.w + bf0.w, 0.f);
        a1.x = fmaxf(a1.x + bf1.x, 0.f); a1.y = fmaxf(a1.y + bf1.y, 0.f);
        a1.z = fmaxf(a1.z + bf1.z, 0.f); a1.w = fmaxf(a1.w + bf1.w, 0.f);
        t4[(size_t)c * 32 + 2 * lane]     = a0;
        t4[(size_t)c * 32 + 2 * lane + 1] = a1;
        s0.x += a0.x; s0.y += a0.y; s0.z += a0.z; s0.w += a0.w;
        s1.x += a1.x; s1.y += a1.y; s1.z += a1.z; s1.w += a1.w;
        ss0.x += a0.x * a0.x; ss0.y += a0.y * a0.y;
        ss0.z += a0.z * a0.z; ss0.w += a0.w * a0.w;
        ss1.x += a1.x * a1.x; ss1.y += a1.y * a1.y;
        ss1.z += a1.z * a1.z; ss1.w += a1.w * a1.w;
    }

    const int fb = 8 * lane;
    atomicAdd(&ssum[fb + 0], s0.x); atomicAdd(&ssum[fb + 1], s0.y);
    atomicAdd(&ssum[fb + 2], s0.z); atomicAdd(&ssum[fb + 3], s0.w);
    atomicAdd(&ssum[fb + 4], s1.x); atomicAdd(&ssum[fb + 5], s1.y);
    atomicAdd(&ssum[fb + 6], s1.z); atomicAdd(&ssum[fb + 7], s1.w);
    atomicAdd(&ssum[FHID + fb + 0], ss0.x); atomicAdd(&ssum[FHID + fb + 1], ss0.y);
    atomicAdd(&ssum[FHID + fb + 2], ss0.z); atomicAdd(&ssum[FHID + fb + 3], ss0.w);
    atomicAdd(&ssum[FHID + fb + 4], ss1.x); atomicAdd(&ssum[FHID + fb + 5], ss1.y);
    atomicAdd(&ssum[FHID + fb + 6], ss1.z); atomicAdd(&ssum[FHID + fb + 7], ss1.w);
    __syncthreads();
    for (int i = threadIdx.x; i < 2 * FHID; i += 256)
        atomicAdd(&g_stats[i], ssum[i]);
}

// out[c] = relu(gather(h2) + b2)
__global__ void __launch_bounds__(256) k_gather2(float* __restrict__ out,
                                                 const float* __restrict__ b2) {
    const int lane = threadIdx.x & 15;
    const int vw   = (blockIdx.x * blockDim.x + threadIdx.x) >> 4;
    const int nvw  = (gridDim.x * blockDim.x) >> 4;
    const float4 bf0 = reinterpret_cast<const float4*>(b2)[2 * lane];
    const float4 bf1 = reinterpret_cast<const float4*>(b2)[2 * lane + 1];
    const uint4* hp = reinterpret_cast<const uint4*>(g_h2);
    float4* o4 = reinterpret_cast<float4*>(out);

    for (int c = vw; c < NNODES; c += nvw) {
        float4 a0, a1;
        gather_node16(hp, c, lane, a0, a1);
        a0.x = fmaxf(a0.x + bf0.x, 0.f); a0.y = fmaxf(a0.y + bf0.y, 0.f);
        a0.z = fmaxf(a0.z + bf0.z, 0.f); a0.w = fmaxf(a0.w + bf0.w, 0.f);
        a1.x = fmaxf(a1.x + bf1.x, 0.f); a1.y = fmaxf(a1.y + bf1.y, 0.f);
        a1.z = fmaxf(a1.z + bf1.z, 0.f); a1.w = fmaxf(a1.w + bf1.w, 0.f);
        o4[(size_t)c * 32 + 2 * lane]     = a0;
        o4[(size_t)c * 32 + 2 * lane + 1] = a1;
    }
}

// ---------------- launch ----------------
extern "C" void kernel_launch(void* const* d_in, const int* in_sizes, int n_in,
                              void* d_out, int out_size) {
    const float* x     = (const float*)d_in[0];
    const void*  ei    = d_in[1];                 // [2, E], int32 OR int64 (detected)
    const float* W1    = (const float*)d_in[2];
    const float* b1    = (const float*)d_in[3];
    const float* gamma = (const float*)d_in[4];
    const float* beta  = (const float*)d_in[5];
    const float* W2    = (const float*)d_in[6];
    const float* b2    = (const float*)d_in[7];
    float* out = (float*)d_out;

    k_zero_detect<<<512, 256>>>((const int*)ei, W1, W2);
    k_deg_gemm1<<<GEMM1_BLOCKS + DEG_BLOCKS, 256>>>(x, ei);
    k_scanA<<<NB_SCAN, 256>>>();
    k_scanC<<<NB_SCAN, 256>>>();
    k_fillcsr<<<FILL_BLOCKS, 256>>>(ei);
    k_gather1<<<1184, 256>>>(b1);
    k_gemm2_mma<<<MPAD / 64, 256>>>(gamma, beta);
    k_gather2<<<1184, 256>>>(out, b2);
}

// round 16
// speedup vs baseline: 1.1957x; 1.1957x over previous
#include <cuda_runtime.h>
#include <cuda_fp16.h>
#include <mma.h>
#include <stdint.h>

using namespace nvcuda;

// GCN_57501022159512: 2-layer GCN, N=100000 nodes, E=1600000 edges, 64 -> 128 -> 128.
// h1 = relu(gcnconv(x, W1, b1)); t = batchnorm(h1); out = relu(gcnconv(t, W2, b2))
//
// R16: layer-1 aggregation moved BEFORE the GEMM (aggregation is linear:
// agg(x@W1) = agg(x)@W1). Gather1 now reads 64-feature fp16 x rows (128B)
// instead of 128-feature h1 rows (256B): random L2 read traffic halved.
// t stored fp16 (halves gemm2 A-read). Gather unroll reverted to R14's x4
// (R15's x8 regressed). gemm1 becomes a wmma epilogue kernel with fused
// bias+ReLU+BN-stats.

#define NNODES 100000
#define NEDGES 1600000
#define FIN    64
#define FHID   128
#define BN_EPS 1e-5f

#define MPAD   100032          // NNODES rounded up to 64 (MMA M-tiles)

#define NB_SCAN 100
#define NODES_PER_BLK 1000     // NNODES / NB_SCAN, exact

#define FILL_BLOCKS  2048
#define TLD 132                // padded smem ldm for fp32 acc staging

// ---------------- scratch (device globals; no allocs allowed) ----------------
__device__ __half  g_xh  [NNODES * FIN];       // x in fp16
__device__ __half  g_aggx[MPAD * FIN];         // agg(x) in fp16 (padded, pad=0)
__device__ __half  g_th  [MPAD * FHID];        // t = relu(aggx@W1+b1), fp16
__device__ __half2 g_h2  [MPAD * (FHID / 2)];  // bn(t) @ W2 (fp16, padded)
__device__ __half  g_W1h[FIN * FHID];          // W1 in fp16 (row-major K x N)
__device__ __half  g_W2h[FHID * FHID];         // W2 in fp16 (row-major K x N)
__device__ float   g_dinv[NNODES];
__device__ int     g_deg [NNODES];
__device__ float   g_stats[2 * FHID];          // sum,sumsq
__device__ int     g_off [NNODES + 1];         // CSR offsets (by destination col)
__device__ int     g_cursor[NNODES];           // placement cursors
__device__ int2    g_csr[NEDGES];              // (src row, norm bits) sorted by dest
__device__ int     g_bsum[NB_SCAN];            // per-block degree sums
__device__ int     g_is64;

// ---------------- helpers ----------------

__device__ __forceinline__ void h16_to_f8(uint4 u, float4& a, float4& b) {
    const float2 f0 = __half22float2(*reinterpret_cast<__half2*>(&u.x));
    const float2 f1 = __half22float2(*reinterpret_cast<__half2*>(&u.y));
    const float2 f2 = __half22float2(*reinterpret_cast<__half2*>(&u.z));
    const float2 f3 = __half22float2(*reinterpret_cast<__half2*>(&u.w));
    a = make_float4(f0.x, f0.y, f1.x, f1.y);
    b = make_float4(f2.x, f2.y, f3.x, f3.y);
}

__device__ __forceinline__ uint4 f8_to_h16(float4 a, float4 b) {
    uint4 u;
    __half2 h0 = __floats2half2_rn(a.x, a.y);
    __half2 h1 = __floats2half2_rn(a.z, a.w);
    __half2 h2 = __floats2half2_rn(b.x, b.y);
    __half2 h3 = __floats2half2_rn(b.z, b.w);
    u.x = *reinterpret_cast<uint32_t*>(&h0);
    u.y = *reinterpret_cast<uint32_t*>(&h1);
    u.z = *reinterpret_cast<uint32_t*>(&h2);
    u.w = *reinterpret_cast<uint32_t*>(&h3);
    return u;
}

__device__ __forceinline__ void fma8(float4& a0, float4& a1, uint4 u, float nm) {
    float4 v0, v1;
    h16_to_f8(u, v0, v1);
    a0.x = fmaf(v0.x, nm, a0.x); a0.y = fmaf(v0.y, nm, a0.y);
    a0.z = fmaf(v0.z, nm, a0.z); a0.w = fmaf(v0.w, nm, a0.w);
    a1.x = fmaf(v1.x, nm, a1.x); a1.y = fmaf(v1.y, nm, a1.y);
    a1.z = fmaf(v1.z, nm, a1.z); a1.w = fmaf(v1.w, nm, a1.w);
}

__device__ __forceinline__ int load_idx(const void* ei, int pos, bool is64) {
    int v = is64 ? (int)((const long long*)ei)[pos] : ((const int*)ei)[pos];
    return min(max(v, 0), NNODES - 1);
}

// ---------------- setup ----------------

// zero deg/stats/aggx-pad; convert W1, W2 -> fp16; block 0 detects edge dtype.
__global__ void k_zero_detect(const int* __restrict__ w,
                              const float* __restrict__ W1,
                              const float* __restrict__ W2) {
    const int idx = blockIdx.x * blockDim.x + threadIdx.x;
    const int stride = gridDim.x * blockDim.x;
    for (int j = idx; j < NNODES; j += stride) g_deg[j] = 0;
    for (int j = idx; j < FIN * FHID; j += stride) g_W1h[j] = __float2half_rn(W1[j]);
    for (int j = idx; j < FHID * FHID; j += stride) g_W2h[j] = __float2half_rn(W2[j]);
    // zero the aggx padding rows [NNODES, MPAD)
    for (int j = idx; j < (MPAD - NNODES) * FIN; j += stride)
        g_aggx[NNODES * FIN + j] = __float2half_rn(0.f);
    if (idx < 2 * FHID) g_stats[idx] = 0.f;

    if (blockIdx.x == 0) {
        __shared__ int bad;
        if (threadIdx.x == 0) bad = 0;
        __syncthreads();
        for (int j = threadIdx.x; j < 1024; j += blockDim.x) {
            const int lo = w[2 * j], hi = w[2 * j + 1];
            if (hi != 0 || lo < 0 || lo >= NNODES) bad = 1;
        }
        __syncthreads();
        if (threadIdx.x == 0) g_is64 = (bad == 0) ? 1 : 0;
    }
}

// degree count (col half) + convert x -> fp16 (independent work, one kernel).
__global__ void k_degx(const void* __restrict__ ei, const float* __restrict__ x) {
    const int idx = blockIdx.x * blockDim.x + threadIdx.x;
    const int stride = gridDim.x * blockDim.x;
    const bool is64 = (g_is64 != 0);
    for (int e = idx; e < NEDGES; e += stride)
        atomicAdd(&g_deg[load_idx(ei, NEDGES + e, is64)], 1);
    for (int j = idx; j < NNODES * FIN; j += stride)
        g_xh[j] = __float2half_rn(x[j]);
}

// Stage A: per-block degree sums.
__global__ void k_scanA() {
    __shared__ int red[256];
    const int b = blockIdx.x;
    const int t = threadIdx.x;
    const int beg = b * NODES_PER_BLK;
    int s = 0;
    for (int i = t; i < NODES_PER_BLK; i += 256) s += g_deg[beg + i];
    red[t] = s;
    __syncthreads();
    for (int d = 128; d > 0; d >>= 1) {
        if (t < d) red[t] += red[t + d];
        __syncthreads();
    }
    if (t == 0) g_bsum[b] = red[0];
}

// Stage C: offsets + cursors + dinv (fused).
__global__ void k_scanC() {
    __shared__ int red[256];
    __shared__ int partial[256];
    __shared__ int s_base;
    const int b = blockIdx.x;
    const int t = threadIdx.x;
    const int beg = b * NODES_PER_BLK;

    int s = (t < b) ? g_bsum[t] : 0;
    red[t] = s;
    __syncthreads();
    for (int d = 128; d > 0; d >>= 1) {
        if (t < d) red[t] += red[t + d];
        __syncthreads();
    }
    if (t == 0) s_base = red[0];
    __syncthreads();

    const int cbeg = t * 4;
    int csum = 0;
    int dloc[4];
#pragma unroll
    for (int j = 0; j < 4; j++) {
        const int i = cbeg + j;
        dloc[j] = (i < NODES_PER_BLK) ? g_deg[beg + i] : 0;
        csum += dloc[j];
    }
    partial[t] = csum;
    __syncthreads();
    for (int d = 1; d < 256; d <<= 1) {
        int v = (t >= d) ? partial[t - d] : 0;
        __syncthreads();
        partial[t] += v;
        __syncthreads();
    }
    int run = s_base + ((t == 0) ? 0 : partial[t - 1]);
#pragma unroll
    for (int j = 0; j < 4; j++) {
        const int i = cbeg + j;
        if (i < NODES_PER_BLK) {
            g_off[beg + i] = run;
            g_cursor[beg + i] = run;
            g_dinv[beg + i] = rsqrtf((float)(dloc[j] + 1));
            run += dloc[j];
        }
    }
    if (b == NB_SCAN - 1 && t == 255) g_off[NNODES] = run;
}

// Counting sort directly from edge buffer.
__global__ void k_fillcsr(const void* __restrict__ ei) {
    const int idx = blockIdx.x * blockDim.x + threadIdx.x;
    const int stride = gridDim.x * blockDim.x;
    const bool is64 = (g_is64 != 0);
    for (int e = idx; e < NEDGES; e += stride) {
        const int r = load_idx(ei, e, is64);
        const int c = load_idx(ei, NEDGES + e, is64);
        const int pos = atomicAdd(&g_cursor[c], 1);
        const float nm = g_dinv[r] * g_dinv[c];
        g_csr[pos] = make_int2(r, __float_as_int(nm));
    }
}

// ---------------- gather over x: 8-lane virtual warps, uint4, unroll x4 ------
// aggx[c] = sum_{e->c} x[r]*norm + x[c]*dinv[c]^2   (64 feats, fp16 in/out)
__global__ void __launch_bounds__(256) k_gather_x() {
    const int lane = threadIdx.x & 7;
    const int vw   = (blockIdx.x * blockDim.x + threadIdx.x) >> 3;
    const int nvw  = (gridDim.x * blockDim.x) >> 3;
    const uint4* xp = reinterpret_cast<const uint4*>(g_xh);
    uint4* ap = reinterpret_cast<uint4*>(g_aggx);

    for (int c = vw; c < NNODES; c += nvw) {
        const int beg = g_off[c], end = g_off[c + 1];
        const float dc = g_dinv[c];
        const float d2 = dc * dc;
        float4 h0, h1;
        h16_to_f8(xp[(size_t)c * 8 + lane], h0, h1);
        float4 a0 = make_float4(h0.x * d2, h0.y * d2, h0.z * d2, h0.w * d2);
        float4 a1 = make_float4(h1.x * d2, h1.y * d2, h1.z * d2, h1.w * d2);
        int i = beg;
        for (; i + 4 <= end; i += 4) {
            const int2 e0 = g_csr[i];
            const int2 e1 = g_csr[i + 1];
            const int2 e2 = g_csr[i + 2];
            const int2 e3 = g_csr[i + 3];
            const uint4 u0 = xp[(size_t)e0.x * 8 + lane];
            const uint4 u1 = xp[(size_t)e1.x * 8 + lane];
            const uint4 u2 = xp[(size_t)e2.x * 8 + lane];
            const uint4 u3 = xp[(size_t)e3.x * 8 + lane];
            fma8(a0, a1, u0, __int_as_float(e0.y));
            fma8(a0, a1, u1, __int_as_float(e1.y));
            fma8(a0, a1, u2, __int_as_float(e2.y));
            fma8(a0, a1, u3, __int_as_float(e3.y));
        }
        for (; i < end; i++) {
            const int2 en = g_csr[i];
            fma8(a0, a1, xp[(size_t)en.x * 8 + lane], __int_as_float(en.y));
        }
        ap[(size_t)c * 8 + lane] = f8_to_h16(a0, a1);
    }
}

// ---------------- gemm1t: t = relu(aggx @ W1 + b1), fused BN stats -----------
__global__ void __launch_bounds__(256) k_gemm1t(const float* __restrict__ b1) {
    __shared__ float sT[64 * TLD];          // 33.8 KB fp32 acc staging
    __shared__ float p0[2][FHID], p1[2][FHID];
    const int t = threadIdx.x;
    const int warp = t >> 5;
    const int base = blockIdx.x * 64;

    wmma::fragment<wmma::matrix_b, 16, 16, 16, __half, wmma::row_major> bf[4];
#pragma unroll
    for (int k = 0; k < 4; k++)
        wmma::load_matrix_sync(bf[k], g_W1h + (k * 16) * FHID + warp * 16, FHID);

#pragma unroll
    for (int m = 0; m < 4; m++) {
        wmma::fragment<wmma::accumulator, 16, 16, 16, float> acc;
        wmma::fill_fragment(acc, 0.0f);
#pragma unroll
        for (int k = 0; k < 4; k++) {
            wmma::fragment<wmma::matrix_a, 16, 16, 16, __half, wmma::row_major> af;
            wmma::load_matrix_sync(af, g_aggx + (size_t)(base + m * 16) * FIN + k * 16, FIN);
            wmma::mma_sync(acc, af, bf[k], acc);
        }
        wmma::store_matrix_sync(sT + (m * 16) * TLD + warp * 16, acc, TLD,
                                wmma::mem_row_major);
    }
    __syncthreads();

    // epilogue: bias + relu + fp16 store + BN partial sums
    const int col = t & 127;
    const int half = t >> 7;             // 0 or 1 -> rows [0,32) or [32,64)
    const float bb = b1[col];
    float s = 0.f, ss = 0.f;
#pragma unroll 4
    for (int j = 0; j < 32; j++) {
        const int row = half * 32 + j;
        const int r = base + row;
        float v = sT[row * TLD + col];
        v = fmaxf(v + bb, 0.f);
        g_th[(size_t)r * FHID + col] = __float2half_rn(v);
        if (r < NNODES) { s += v; ss += v * v; }
    }
    p0[half][col] = s;
    p1[half][col] = ss;
    __syncthreads();
    if (half == 0) {
        atomicAdd(&g_stats[col], p0[0][col] + p0[1][col]);
        atomicAdd(&g_stats[FHID + col], p1[0][col] + p1[1][col]);
    }
}

// ---------------- GEMM2 on tensor cores (fp16 t in, fp16 h2 out) -------------
__global__ void __launch_bounds__(256) k_gemm2_mma(const float* __restrict__ gamma,
                                                   const float* __restrict__ beta) {
    __shared__ __half  sA[64 * FHID];       // 16 KB
    __shared__ float   sScale[FHID], sShift[FHID];
    const int t = threadIdx.x;
    const int warp = t >> 5;
    const int base = blockIdx.x * 64;

    if (t < FHID) {
        const float inv_n = 1.0f / (float)NNODES;
        const float mean = g_stats[t] * inv_n;
        const float var  = g_stats[FHID + t] * inv_n - mean * mean;
        const float rstd = rsqrtf(var + BN_EPS);
        const float sc = gamma[t] * rstd;
        sScale[t] = sc;
        sShift[t] = beta[t] - mean * sc;
    }
    __syncthreads();

    for (int i = t; i < 64 * FHID; i += 256) {
        const int c = i & 127;
        const float v = __half2float(g_th[(size_t)(base + (i >> 7)) * FHID + c]);
        sA[i] = __float2half_rn(fmaf(v, sScale[c], sShift[c]));
    }
    __syncthreads();

    wmma::fragment<wmma::matrix_b, 16, 16, 16, __half, wmma::row_major> bf[8];
#pragma unroll
    for (int k = 0; k < 8; k++)
        wmma::load_matrix_sync(bf[k], g_W2h + (k * 16) * FHID + warp * 16, FHID);

    __half* h2 = reinterpret_cast<__half*>(g_h2);
#pragma unroll
    for (int m = 0; m < 4; m++) {
        wmma::fragment<wmma::accumulator, 16, 16, 16, float> acc;
        wmma::fill_fragment(acc, 0.0f);
#pragma unroll
        for (int k = 0; k < 8; k++) {
            wmma::fragment<wmma::matrix_a, 16, 16, 16, __half, wmma::row_major> af;
            wmma::load_matrix_sync(af, sA + (m * 16) * FHID + k * 16, FHID);
            wmma::mma_sync(acc, af, bf[k], acc);
        }
        wmma::fragment<wmma::accumulator, 16, 16, 16, __half> hacc;
#pragma unroll
        for (int i = 0; i < acc.num_elements; i++)
            hacc.x[i] = __float2half_rn(acc.x[i]);
        wmma::store_matrix_sync(h2 + (size_t)(base + m * 16) * FHID + warp * 16,
                                hacc, FHID, wmma::mem_row_major);
    }
}

// ---------------- gather2: 16-lane virtual warps, uint4 rows, unroll x4 ------
__global__ void __launch_bounds__(256) k_gather2(float* __restrict__ out,
                                                 const float* __restrict__ b2) {
    const int lane = threadIdx.x & 15;
    const int vw   = (blockIdx.x * blockDim.x + threadIdx.x) >> 4;
    const int nvw  = (gridDim.x * blockDim.x) >> 4;
    const float4 bf0 = reinterpret_cast<const float4*>(b2)[2 * lane];
    const float4 bf1 = reinterpret_cast<const float4*>(b2)[2 * lane + 1];
    const uint4* hp = reinterpret_cast<const uint4*>(g_h2);
    float4* o4 = reinterpret_cast<float4*>(out);

    for (int c = vw; c < NNODES; c += nvw) {
        const int beg = g_off[c], end = g_off[c + 1];
        const float dc = g_dinv[c];
        const float d2 = dc * dc;
        float4 h0, h1;
        h16_to_f8(hp[(size_t)c * 16 + lane], h0, h1);
        float4 a0 = make_float4(h0.x * d2, h0.y * d2, h0.z * d2, h0.w * d2);
        float4 a1 = make_float4(h1.x * d2, h1.y * d2, h1.z * d2, h1.w * d2);
        int i = beg;
        for (; i + 4 <= end; i += 4) {
            const int2 e0 = g_csr[i];
            const int2 e1 = g_csr[i + 1];
            const int2 e2 = g_csr[i + 2];
            const int2 e3 = g_csr[i + 3];
            const uint4 u0 = hp[(size_t)e0.x * 16 + lane];
            const uint4 u1 = hp[(size_t)e1.x * 16 + lane];
            const uint4 u2 = hp[(size_t)e2.x * 16 + lane];
            const uint4 u3 = hp[(size_t)e3.x * 16 + lane];
            fma8(a0, a1, u0, __int_as_float(e0.y));
            fma8(a0, a1, u1, __int_as_float(e1.y));
            fma8(a0, a1, u2, __int_as_float(e2.y));
            fma8(a0, a1, u3, __int_as_float(e3.y));
        }
        for (; i < end; i++) {
            const int2 en = g_csr[i];
            fma8(a0, a1, hp[(size_t)en.x * 16 + lane], __int_as_float(en.y));
        }
        a0.x = fmaxf(a0.x + bf0.x, 0.f); a0.y = fmaxf(a0.y + bf0.y, 0.f);
        a0.z = fmaxf(a0.z + bf0.z, 0.f); a0.w = fmaxf(a0.w + bf0.w, 0.f);
        a1.x = fmaxf(a1.x + bf1.x, 0.f); a1.y = fmaxf(a1.y + bf1.y, 0.f);
        a1.z = fmaxf(a1.z + bf1.z, 0.f); a1.w = fmaxf(a1.w + bf1.w, 0.f);
        o4[(size_t)c * 32 + 2 * lane]     = a0;
        o4[(size_t)c * 32 + 2 * lane + 1] = a1;
    }
}

// ---------------- launch ----------------
extern "C" void kernel_launch(void* const* d_in, const int* in_sizes, int n_in,
                              void* d_out, int out_size) {
    const float* x     = (const float*)d_in[0];
    const void*  ei    = d_in[1];                 // [2, E], int32 OR int64 (detected)
    const float* W1    = (const float*)d_in[2];
    const float* b1    = (const float*)d_in[3];
    const float* gamma = (const float*)d_in[4];
    const float* beta  = (const float*)d_in[5];
    const float* W2    = (const float*)d_in[6];
    const float* b2    = (const float*)d_in[7];
    float* out = (float*)d_out;

    k_zero_detect<<<512, 256>>>((const int*)ei, W1, W2);
    k_degx<<<2048, 256>>>(ei, x);
    k_scanA<<<NB_SCAN, 256>>>();
    k_scanC<<<NB_SCAN, 256>>>();
    k_fillcsr<<<FILL_BLOCKS, 256>>>(ei);
    k_gather_x<<<1184, 256>>>();
    k_gemm1t<<<MPAD / 64, 256>>>(b1);
    k_gemm2_mma<<<MPAD / 64, 256>>>(gamma, beta);
    k_gather2<<<1184, 256>>>(out, b2);
}